// round 3
// baseline (speedup 1.0000x reference)
#include <cuda_runtime.h>
#include <math.h>
#include <stdint.h>

#define B_      256
#define T_      256
#define D_      512
#define UNITS_  1024
#define NCL_    512
#define FOURU_  4096

// ---------------- static device scratch (no allocs allowed) ----------------
__device__ float g_Zx[(size_t)T_ * B_ * FOURU_];   // [t][b][j'] = x_t @ Wx (permuted), NO bias
__device__ float g_Uperm[(size_t)UNITS_ * FOURU_];
__device__ float g_Wxperm[(size_t)D_ * FOURU_];
__device__ float g_Wwperm[(size_t)NCL_ * FOURU_];
__device__ float g_bperm[FOURU_];
__device__ float g_h0[B_ * UNITS_];
__device__ float g_h1[B_ * UNITS_];
__device__ float g_c[B_ * UNITS_];
__device__ int   g_idx[B_];
__device__ float g_lpart[(size_t)8 * B_ * NCL_];

// ---------------- helpers ----------------
// Keras hard_sigmoid exactly as XLA evaluates it: mul, add (separately rounded), clamp.
__device__ __forceinline__ float hsig(float z) {
    float t = __fadd_rn(__fmul_rn(0.2f, z), 0.5f);
    return fminf(fmaxf(t, 0.0f), 1.0f);
}

// XLA's f32 tanh lowering, replicated exactly:
//   |x| < 0.0004           -> x
//   else clamp x to [-9,9] -> rational P13(x)/Q6(x) with fmuladd polynomial, IEEE divide
__device__ __forceinline__ float tanh_xla(float x) {
    float ax = fabsf(x);
    if (ax < 0.0004f) return x;
    float xc = fminf(fmaxf(x, -9.0f), 9.0f);
    float x2 = __fmul_rn(xc, xc);
    float p = -2.76076847742355e-16f;
    p = fmaf(p, x2, 2.00018790482477e-13f);
    p = fmaf(p, x2, -8.60467152213735e-11f);
    p = fmaf(p, x2, 5.12229709037114e-08f);
    p = fmaf(p, x2, 1.48572235717979e-05f);
    p = fmaf(p, x2, 6.37261928875436e-04f);
    p = fmaf(p, x2, 4.89352455891786e-03f);
    float num = __fmul_rn(xc, p);
    float q = 1.19825839466702e-06f;
    q = fmaf(q, x2, 1.18534705686654e-04f);
    q = fmaf(q, x2, 2.26843463243900e-03f);
    q = fmaf(q, x2, 4.89352518554385e-03f);
    return __fdiv_rn(num, q);
}

// ---------------- init ----------------
__global__ void init_kernel() {
    int stride = gridDim.x * blockDim.x;
    for (int i = blockIdx.x * blockDim.x + threadIdx.x; i < B_ * UNITS_; i += stride) {
        g_h0[i] = 0.0f;
        g_c[i] = 0.0f;
        if (i < B_) g_idx[i] = -1;
    }
}

// ---------------- permute to gate-interleaved column order j' = 4u + g ----------------
__global__ void permute_kernel(const float* __restrict__ W,
                               const float* __restrict__ U,
                               const float* __restrict__ b) {
    int stride = gridDim.x * blockDim.x;
    for (int i = blockIdx.x * blockDim.x + threadIdx.x; i < UNITS_ * FOURU_; i += stride) {
        int k  = i >> 12;
        int jp = i & 4095;
        int src = ((jp & 3) << 10) + (jp >> 2);   // g*1024 + u
        g_Uperm[i] = U[((size_t)k << 12) + src];
        if (k < D_)   g_Wxperm[(size_t)k * FOURU_ + jp] = W[((size_t)k << 12) + src];
        if (k < NCL_) g_Wwperm[(size_t)k * FOURU_ + jp] = W[((size_t)(k + D_) << 12) + src];
        if (k == 0)   g_bperm[jp] = b[src];
    }
}

// ---------------- GEMM tile config: 128x64x16, 256 threads, 4x8/thread ----------------
#define BM 128
#define BN 64
#define BK 16
#define ASTRIDE (BM + 4)

// ---------------- precompute Zx = x @ Wxperm (no bias), stored [t][b][:] ----------------
__global__ void __launch_bounds__(256) precompute_kernel(const float* __restrict__ x) {
    __shared__ float As[BK][ASTRIDE];
    __shared__ float Bs[BK][BN];
    int tid = threadIdx.x;
    int tx = tid & 7, ty = tid >> 3;
    int m0 = blockIdx.y * BM;
    int n0 = blockIdx.x * BN;

    float acc[4][8];
#pragma unroll
    for (int i = 0; i < 4; i++)
#pragma unroll
        for (int j = 0; j < 8; j++) acc[i][j] = 0.0f;

    for (int k0 = 0; k0 < D_; k0 += BK) {
#pragma unroll
        for (int l = 0; l < 2; l++) {
            int e = l * 256 + tid;
            int row = e >> 2, c4 = e & 3;
            float4 v = *(const float4*)&x[(size_t)(m0 + row) * D_ + k0 + c4 * 4];
            As[c4 * 4 + 0][row] = v.x;
            As[c4 * 4 + 1][row] = v.y;
            As[c4 * 4 + 2][row] = v.z;
            As[c4 * 4 + 3][row] = v.w;
        }
        {
            int row = tid >> 4, c4 = tid & 15;
            *(float4*)&Bs[row][c4 * 4] =
                *(const float4*)&g_Wxperm[(size_t)(k0 + row) * FOURU_ + n0 + c4 * 4];
        }
        __syncthreads();
#pragma unroll
        for (int kk = 0; kk < BK; kk++) {
            float a[4], bb[8];
#pragma unroll
            for (int i = 0; i < 4; i++) a[i] = As[kk][ty * 4 + i];
#pragma unroll
            for (int j = 0; j < 8; j++) bb[j] = Bs[kk][tx * 8 + j];
#pragma unroll
            for (int i = 0; i < 4; i++)
#pragma unroll
                for (int j = 0; j < 8; j++) acc[i][j] = fmaf(a[i], bb[j], acc[i][j]);
        }
        __syncthreads();
    }

#pragma unroll
    for (int i = 0; i < 4; i++) {
        int m = m0 + ty * 4 + i;       // m = b*T + t
        int b = m >> 8;
        int t = m & 255;
        float* dst = &g_Zx[((size_t)t * B_ + b) * FOURU_ + n0 + tx * 8];
#pragma unroll
        for (int j = 0; j < 8; j++) dst[j] = acc[i][j];
    }
}

// ---------------- per-step: z = ((Zx[t] + Ww[idx]) + h@U) + b; fused gates ----------------
__global__ void __launch_bounds__(256) step_kernel(int t) {
    const float* __restrict__ h_in = (t & 1) ? g_h1 : g_h0;
    float* __restrict__ h_out = (t & 1) ? g_h0 : g_h1;

    __shared__ float As[BK][ASTRIDE];
    __shared__ float Bs[BK][BN];
    int tid = threadIdx.x;
    int tx = tid & 7, ty = tid >> 3;
    int m0 = blockIdx.y * BM;
    int n0 = blockIdx.x * BN;

    float acc[4][8];
#pragma unroll
    for (int i = 0; i < 4; i++)
#pragma unroll
        for (int j = 0; j < 8; j++) acc[i][j] = 0.0f;

    for (int k0 = 0; k0 < UNITS_; k0 += BK) {
#pragma unroll
        for (int l = 0; l < 2; l++) {
            int e = l * 256 + tid;
            int row = e >> 2, c4 = e & 3;
            float4 v = *(const float4*)&h_in[(size_t)(m0 + row) * UNITS_ + k0 + c4 * 4];
            As[c4 * 4 + 0][row] = v.x;
            As[c4 * 4 + 1][row] = v.y;
            As[c4 * 4 + 2][row] = v.z;
            As[c4 * 4 + 3][row] = v.w;
        }
        {
            int row = tid >> 4, c4 = tid & 15;
            *(float4*)&Bs[row][c4 * 4] =
                *(const float4*)&g_Uperm[(size_t)(k0 + row) * FOURU_ + n0 + c4 * 4];
        }
        __syncthreads();
#pragma unroll
        for (int kk = 0; kk < BK; kk++) {
            float a[4], bb[8];
#pragma unroll
            for (int i = 0; i < 4; i++) a[i] = As[kk][ty * 4 + i];
#pragma unroll
            for (int j = 0; j < 8; j++) bb[j] = Bs[kk][tx * 8 + j];
#pragma unroll
            for (int i = 0; i < 4; i++)
#pragma unroll
                for (int j = 0; j < 8; j++) acc[i][j] = fmaf(a[i], bb[j], acc[i][j]);
        }
        __syncthreads();
    }

    int ncol = n0 + tx * 8;            // 8 cols = 2 complete gate quadruples
#pragma unroll
    for (int i = 0; i < 4; i++) {
        int b = m0 + ty * 4 + i;
        int idx = g_idx[b];
        const float* zx = &g_Zx[((size_t)t * B_ + b) * FOURU_ + ncol];
        float z[8];
        if (idx >= 0) {
            const float* ww = &g_Wwperm[(size_t)idx * FOURU_ + ncol];
#pragma unroll
            for (int j = 0; j < 8; j++) {
                float insW = __fadd_rn(zx[j], ww[j]);
                z[j] = __fadd_rn(__fadd_rn(insW, acc[i][j]), g_bperm[ncol + j]);
            }
        } else {
#pragma unroll
            for (int j = 0; j < 8; j++)
                z[j] = __fadd_rn(__fadd_rn(zx[j], acc[i][j]), g_bperm[ncol + j]);
        }
#pragma unroll
        for (int uu = 0; uu < 2; uu++) {
            float zi = z[uu * 4 + 0], zf = z[uu * 4 + 1];
            float zc = z[uu * 4 + 2], zo = z[uu * 4 + 3];
            int u = (ncol >> 2) + uu;
            float cold = g_c[b * UNITS_ + u];
            // c_new = hs(zf)*c + hs(zi)*tanh(zc)  -- mul, mul, add, all separately rounded
            float m1 = __fmul_rn(hsig(zf), cold);
            float m2 = __fmul_rn(hsig(zi), tanh_xla(zc));
            float cn = __fadd_rn(m1, m2);
            float hn = __fmul_rn(hsig(zo), tanh_xla(cn));
            g_c[b * UNITS_ + u] = cn;
            h_out[b * UNITS_ + u] = hn;
        }
    }
}

// ---------------- logits partials: h_new @ Wout, K split x8 ----------------
__global__ void __launch_bounds__(256) logits_kernel(const float* __restrict__ Wout, int t) {
    const float* __restrict__ h = (t & 1) ? g_h0 : g_h1;   // h_new written by step t

    __shared__ float As[BK][ASTRIDE];
    __shared__ float Bs[BK][BN];
    int tid = threadIdx.x;
    int tx = tid & 7, ty = tid >> 3;
    int m0 = blockIdx.y * BM;
    int n0 = blockIdx.x * BN;
    int kc = blockIdx.z;
    int kbeg = kc * 128;

    float acc[4][8];
#pragma unroll
    for (int i = 0; i < 4; i++)
#pragma unroll
        for (int j = 0; j < 8; j++) acc[i][j] = 0.0f;

    for (int k0 = kbeg; k0 < kbeg + 128; k0 += BK) {
#pragma unroll
        for (int l = 0; l < 2; l++) {
            int e = l * 256 + tid;
            int row = e >> 2, c4 = e & 3;
            float4 v = *(const float4*)&h[(size_t)(m0 + row) * UNITS_ + k0 + c4 * 4];
            As[c4 * 4 + 0][row] = v.x;
            As[c4 * 4 + 1][row] = v.y;
            As[c4 * 4 + 2][row] = v.z;
            As[c4 * 4 + 3][row] = v.w;
        }
        {
            int row = tid >> 4, c4 = tid & 15;
            *(float4*)&Bs[row][c4 * 4] =
                *(const float4*)&Wout[(size_t)(k0 + row) * NCL_ + n0 + c4 * 4];
        }
        __syncthreads();
#pragma unroll
        for (int kk = 0; kk < BK; kk++) {
            float a[4], bb[8];
#pragma unroll
            for (int i = 0; i < 4; i++) a[i] = As[kk][ty * 4 + i];
#pragma unroll
            for (int j = 0; j < 8; j++) bb[j] = Bs[kk][tx * 8 + j];
#pragma unroll
            for (int i = 0; i < 4; i++)
#pragma unroll
                for (int j = 0; j < 8; j++) acc[i][j] = fmaf(a[i], bb[j], acc[i][j]);
        }
        __syncthreads();
    }

#pragma unroll
    for (int i = 0; i < 4; i++) {
        int m = m0 + ty * 4 + i;
        float* dst = &g_lpart[((size_t)kc * B_ + m) * NCL_ + n0 + tx * 8];
#pragma unroll
        for (int j = 0; j < 8; j++) dst[j] = acc[i][j];
    }
}

// ---------------- reduce partials + bias, argmax (tie -> lowest index) ----------------
__global__ void __launch_bounds__(256) argmax_kernel(const float* __restrict__ bout,
                                                     float* __restrict__ out, int t) {
    int b = blockIdx.x;
    int tid = threadIdx.x;
    unsigned long long best = 0ull;
    for (int n = tid; n < NCL_; n += 256) {
        float l = 0.0f;
#pragma unroll
        for (int kc = 0; kc < 8; kc++)
            l = __fadd_rn(l, g_lpart[((size_t)kc * B_ + b) * NCL_ + n]);
        l = __fadd_rn(l, bout[n]);   // bias added last, matching (h@Wout) + bout
        unsigned u = __float_as_uint(l);
        u = (u & 0x80000000u) ? ~u : (u | 0x80000000u);
        unsigned long long key = ((unsigned long long)u << 32) | (unsigned)(NCL_ - 1 - n);
        best = best > key ? best : key;
    }
    __shared__ unsigned long long red[256];
    red[tid] = best;
    __syncthreads();
    for (int s = 128; s > 0; s >>= 1) {
        if (tid < s) red[tid] = red[tid] > red[tid + s] ? red[tid] : red[tid + s];
        __syncthreads();
    }
    if (tid == 0) {
        int idx = (NCL_ - 1) - (int)(red[0] & 0xffffffffu);
        g_idx[b] = idx;
        out[(size_t)b * T_ + t] = (float)idx;   // output dtype: float32
    }
}

// ---------------- launch ----------------
extern "C" void kernel_launch(void* const* d_in, const int* in_sizes, int n_in,
                              void* d_out, int out_size) {
    (void)out_size;
    // Resolve inputs by element count (robust to metadata ordering).
    const float *x = 0, *W = 0, *U = 0, *b = 0, *Wout = 0, *bout = 0;
    const float* big[2] = {0, 0};
    int nbig = 0;
    for (int i = 0; i < n_in; i++) {
        switch (in_sizes[i]) {
            case 33554432: x    = (const float*)d_in[i]; break;  // 256*256*512
            case 524288:   Wout = (const float*)d_in[i]; break;  // 1024*512
            case 4096:     b    = (const float*)d_in[i]; break;
            case 512:      bout = (const float*)d_in[i]; break;
            case 4194304:  if (nbig < 2) big[nbig++] = (const float*)d_in[i]; break;
            default: break;
        }
    }
    W = big[0];   // first 4.19M-element tensor in metadata order
    U = big[1];
    float* out = (float*)d_out;

    init_kernel<<<512, 256>>>();
    permute_kernel<<<2048, 256>>>(W, U, b);
    precompute_kernel<<<dim3(FOURU_ / BN, (B_ * T_) / BM), 256>>>(x);

    for (int t = 0; t < T_; t++) {
        step_kernel<<<dim3(FOURU_ / BN, B_ / BM), 256>>>(t);
        logits_kernel<<<dim3(NCL_ / BN, B_ / BM, 8), 256>>>(Wout, t);
        argmax_kernel<<<B_, 256>>>(bout, out, t);
    }
}

// round 7
// speedup vs baseline: 1.2953x; 1.2953x over previous
#include <cuda_runtime.h>
#include <math.h>
#include <stdint.h>

#define B_      256
#define T_      256
#define D_      512
#define UNITS_  1024
#define NCL_    512
#define FOURU_  4096

// ---------------- static device scratch (no allocs allowed) ----------------
__device__ float g_Zx[(size_t)T_ * B_ * FOURU_];     // [t][b][j'] = x_t @ Wx (permuted), NO bias
__device__ float g_Uperm[(size_t)UNITS_ * FOURU_];
__device__ float g_Wxperm[(size_t)D_ * FOURU_];
__device__ float g_Wwperm[(size_t)NCL_ * FOURU_];
__device__ float g_bperm[FOURU_];
__device__ float g_h0[B_ * UNITS_];
__device__ float g_h1[B_ * UNITS_];
__device__ float g_c[B_ * UNITS_];
__device__ int   g_idx[B_];
__device__ float g_lpart[(size_t)8 * B_ * NCL_];     // logit partials

// ---------------- helpers ----------------
__device__ __forceinline__ float hsig(float z) {
    float t = __fadd_rn(__fmul_rn(0.2f, z), 0.5f);
    return fminf(fmaxf(t, 0.0f), 1.0f);
}
// XLA's f32 tanh lowering, replicated exactly.
__device__ __forceinline__ float tanh_xla(float x) {
    float ax = fabsf(x);
    if (ax < 0.0004f) return x;
    float xc = fminf(fmaxf(x, -9.0f), 9.0f);
    float x2 = __fmul_rn(xc, xc);
    float p = -2.76076847742355e-16f;
    p = fmaf(p, x2, 2.00018790482477e-13f);
    p = fmaf(p, x2, -8.60467152213735e-11f);
    p = fmaf(p, x2, 5.12229709037114e-08f);
    p = fmaf(p, x2, 1.48572235717979e-05f);
    p = fmaf(p, x2, 6.37261928875436e-04f);
    p = fmaf(p, x2, 4.89352455891786e-03f);
    float num = __fmul_rn(xc, p);
    float q = 1.19825839466702e-06f;
    q = fmaf(q, x2, 1.18534705686654e-04f);
    q = fmaf(q, x2, 2.26843463243900e-03f);
    q = fmaf(q, x2, 4.89352518554385e-03f);
    return __fdiv_rn(num, q);
}

// ---------------- init ----------------
__global__ void init_kernel() {
    int stride = gridDim.x * blockDim.x;
    for (int i = blockIdx.x * blockDim.x + threadIdx.x; i < B_ * UNITS_; i += stride) {
        g_h0[i] = 0.0f;
        g_c[i] = 0.0f;
        if (i < B_) g_idx[i] = -1;
    }
}

// ---------------- permute to gate-interleaved column order j' = 4u + g ----------------
__global__ void permute_kernel(const float* __restrict__ W,
                               const float* __restrict__ U,
                               const float* __restrict__ b) {
    int stride = gridDim.x * blockDim.x;
    for (int i = blockIdx.x * blockDim.x + threadIdx.x; i < UNITS_ * FOURU_; i += stride) {
        int k  = i >> 12;
        int jp = i & 4095;
        int src = ((jp & 3) << 10) + (jp >> 2);   // g*1024 + u
        g_Uperm[i] = U[((size_t)k << 12) + src];
        if (k < D_)   g_Wxperm[(size_t)k * FOURU_ + jp] = W[((size_t)k << 12) + src];
        if (k < NCL_) g_Wwperm[(size_t)k * FOURU_ + jp] = W[((size_t)(k + D_) << 12) + src];
        if (k == 0)   g_bperm[jp] = b[src];
    }
}

// ---------------- precompute GEMM tile: 128x64x16, 256 threads, 4x8/thread ----------------
#define BM 128
#define BN 64
#define BK 16
#define ASTRIDE (BM + 4)   // 132 floats; row base 528B = 16B aligned

__global__ void __launch_bounds__(256) precompute_kernel(const float* __restrict__ x) {
    __shared__ float As[BK][ASTRIDE];
    __shared__ float Bs[BK][BN];
    int tid = threadIdx.x;
    int tx = tid & 7, ty = tid >> 3;
    int m0 = blockIdx.y * BM;
    int n0 = blockIdx.x * BN;

    float acc[4][8];
#pragma unroll
    for (int i = 0; i < 4; i++)
#pragma unroll
        for (int j = 0; j < 8; j++) acc[i][j] = 0.0f;

    for (int k0 = 0; k0 < D_; k0 += BK) {
#pragma unroll
        for (int l = 0; l < 2; l++) {
            int e = l * 256 + tid;
            int row = e >> 2, c4 = e & 3;
            float4 v = *(const float4*)&x[(size_t)(m0 + row) * D_ + k0 + c4 * 4];
            As[c4 * 4 + 0][row] = v.x;
            As[c4 * 4 + 1][row] = v.y;
            As[c4 * 4 + 2][row] = v.z;
            As[c4 * 4 + 3][row] = v.w;
        }
        {
            int row = tid >> 4, c4 = tid & 15;
            *(float4*)&Bs[row][c4 * 4] =
                *(const float4*)&g_Wxperm[(size_t)(k0 + row) * FOURU_ + n0 + c4 * 4];
        }
        __syncthreads();
#pragma unroll
        for (int kk = 0; kk < BK; kk++) {
            float4 a4 = *(const float4*)&As[kk][ty * 4];
            float4 b0 = *(const float4*)&Bs[kk][tx * 8];
            float4 b1 = *(const float4*)&Bs[kk][tx * 8 + 4];
            float a[4] = {a4.x, a4.y, a4.z, a4.w};
            float bb[8] = {b0.x, b0.y, b0.z, b0.w, b1.x, b1.y, b1.z, b1.w};
#pragma unroll
            for (int i = 0; i < 4; i++)
#pragma unroll
                for (int j = 0; j < 8; j++) acc[i][j] = fmaf(a[i], bb[j], acc[i][j]);
        }
        __syncthreads();
    }

#pragma unroll
    for (int i = 0; i < 4; i++) {
        int m = m0 + ty * 4 + i;       // m = b*T + t
        int b = m >> 8;
        int t = m & 255;
        float* dst = &g_Zx[((size_t)t * B_ + b) * FOURU_ + n0 + tx * 8];
        *(float4*)&dst[0] = make_float4(acc[i][0], acc[i][1], acc[i][2], acc[i][3]);
        *(float4*)&dst[4] = make_float4(acc[i][4], acc[i][5], acc[i][6], acc[i][7]);
    }
}

// ---------------- fused step: 64x64 tile, full K, gates in epilogue ----------------
#define SBM 64
#define SBN 64
#define SASTRIDE (SBM + 4)   // 68 floats; row base 272B = 16B aligned

__global__ void __launch_bounds__(256) step_kernel(int t) {
    const float* __restrict__ h_in = (t & 1) ? g_h1 : g_h0;
    float* __restrict__ h_out = (t & 1) ? g_h0 : g_h1;

    __shared__ float As[BK][SASTRIDE];
    __shared__ float Bs[BK][SBN];
    int tid = threadIdx.x;
    int tx = tid & 15, ty = tid >> 4;
    int m0 = blockIdx.y * SBM;
    int n0 = blockIdx.x * SBN;

    float acc[4][4];
#pragma unroll
    for (int i = 0; i < 4; i++)
#pragma unroll
        for (int j = 0; j < 4; j++) acc[i][j] = 0.0f;

    for (int k0 = 0; k0 < UNITS_; k0 += BK) {
        {
            int row = tid >> 2, c4 = tid & 3;
            float4 v = *(const float4*)&h_in[(size_t)(m0 + row) * UNITS_ + k0 + c4 * 4];
            As[c4 * 4 + 0][row] = v.x;
            As[c4 * 4 + 1][row] = v.y;
            As[c4 * 4 + 2][row] = v.z;
            As[c4 * 4 + 3][row] = v.w;
        }
        {
            int row = tid >> 4, c4 = tid & 15;
            *(float4*)&Bs[row][c4 * 4] =
                *(const float4*)&g_Uperm[(size_t)(k0 + row) * FOURU_ + n0 + c4 * 4];
        }
        __syncthreads();
#pragma unroll
        for (int kk = 0; kk < BK; kk++) {
            float4 a4 = *(const float4*)&As[kk][ty * 4];
            float4 b4 = *(const float4*)&Bs[kk][tx * 4];
            float a[4] = {a4.x, a4.y, a4.z, a4.w};
            float bb[4] = {b4.x, b4.y, b4.z, b4.w};
#pragma unroll
            for (int i = 0; i < 4; i++)
#pragma unroll
                for (int j = 0; j < 4; j++) acc[i][j] = fmaf(a[i], bb[j], acc[i][j]);
        }
        __syncthreads();
    }

    // epilogue: each thread's 4 columns = one complete gate quadruple
    int jbase = n0 + tx * 4;
    int u = jbase >> 2;
    float4 bb4 = *(const float4*)&g_bperm[jbase];
    float bv[4] = {bb4.x, bb4.y, bb4.z, bb4.w};
#pragma unroll
    for (int i = 0; i < 4; i++) {
        int b = m0 + ty * 4 + i;
        int idx = g_idx[b];
        float4 zx4 = *(const float4*)&g_Zx[((size_t)t * B_ + b) * FOURU_ + jbase];
        float ins[4] = {zx4.x, zx4.y, zx4.z, zx4.w};
        if (idx >= 0) {
            float4 ww = *(const float4*)&g_Wwperm[(size_t)idx * FOURU_ + jbase];
            ins[0] = __fadd_rn(ins[0], ww.x);
            ins[1] = __fadd_rn(ins[1], ww.y);
            ins[2] = __fadd_rn(ins[2], ww.z);
            ins[3] = __fadd_rn(ins[3], ww.w);
        }
        float z[4];
#pragma unroll
        for (int g = 0; g < 4; g++)
            z[g] = __fadd_rn(__fadd_rn(ins[g], acc[i][g]), bv[g]);

        float cold = g_c[b * UNITS_ + u];
        float m1 = __fmul_rn(hsig(z[1]), cold);
        float m2 = __fmul_rn(hsig(z[0]), tanh_xla(z[2]));
        float cn = __fadd_rn(m1, m2);
        float hn = __fmul_rn(hsig(z[3]), tanh_xla(cn));
        g_c[b * UNITS_ + u] = cn;
        h_out[b * UNITS_ + u] = hn;
    }
}

// ---------------- logits partials: h_new @ Wout, 64x64 tiles, K split x8 ----------------
#define LBM 64
#define LBN 64
#define LASTRIDE (LBM + 4)

__global__ void __launch_bounds__(256) logits_kernel(const float* __restrict__ Wout, int t) {
    const float* __restrict__ h = (t & 1) ? g_h0 : g_h1;   // h_new written by step t

    __shared__ float As[BK][LASTRIDE];
    __shared__ float Bs[BK][LBN];
    int tid = threadIdx.x;
    int tx = tid & 15, ty = tid >> 4;
    int m0 = blockIdx.y * LBM;
    int n0 = blockIdx.x * LBN;
    int kc = blockIdx.z;
    int kbeg = kc * 128;

    float acc[4][4];
#pragma unroll
    for (int i = 0; i < 4; i++)
#pragma unroll
        for (int j = 0; j < 4; j++) acc[i][j] = 0.0f;

    for (int k0 = kbeg; k0 < kbeg + 128; k0 += BK) {
        {
            int row = tid >> 2, c4 = tid & 3;
            float4 v = *(const float4*)&h[(size_t)(m0 + row) * UNITS_ + k0 + c4 * 4];
            As[c4 * 4 + 0][row] = v.x;
            As[c4 * 4 + 1][row] = v.y;
            As[c4 * 4 + 2][row] = v.z;
            As[c4 * 4 + 3][row] = v.w;
        }
        {
            int row = tid >> 4, c4 = tid & 15;
            *(float4*)&Bs[row][c4 * 4] =
                *(const float4*)&Wout[(size_t)(k0 + row) * NCL_ + n0 + c4 * 4];
        }
        __syncthreads();
#pragma unroll
        for (int kk = 0; kk < BK; kk++) {
            float4 a4 = *(const float4*)&As[kk][ty * 4];
            float4 b4 = *(const float4*)&Bs[kk][tx * 4];
            float a[4] = {a4.x, a4.y, a4.z, a4.w};
            float bb[4] = {b4.x, b4.y, b4.z, b4.w};
#pragma unroll
            for (int i = 0; i < 4; i++)
#pragma unroll
                for (int j = 0; j < 4; j++) acc[i][j] = fmaf(a[i], bb[j], acc[i][j]);
        }
        __syncthreads();
    }

#pragma unroll
    for (int i = 0; i < 4; i++) {
        int m = m0 + ty * 4 + i;
        float* dst = &g_lpart[((size_t)kc * B_ + m) * NCL_ + n0 + tx * 4];
        *(float4*)dst = make_float4(acc[i][0], acc[i][1], acc[i][2], acc[i][3]);
    }
}

// ---------------- reduce partials + bias, argmax (tie -> lowest index) ----------------
__global__ void __launch_bounds__(256) argmax_kernel(const float* __restrict__ bout,
                                                     float* __restrict__ out, int t) {
    int b = blockIdx.x;
    int tid = threadIdx.x;
    unsigned long long best = 0ull;
    for (int n = tid; n < NCL_; n += 256) {
        float l = 0.0f;
#pragma unroll
        for (int kc = 0; kc < 8; kc++)
            l = __fadd_rn(l, g_lpart[((size_t)kc * B_ + b) * NCL_ + n]);
        l = __fadd_rn(l, bout[n]);
        unsigned u = __float_as_uint(l);
        u = (u & 0x80000000u) ? ~u : (u | 0x80000000u);
        unsigned long long key = ((unsigned long long)u << 32) | (unsigned)(NCL_ - 1 - n);
        best = best > key ? best : key;
    }
    __shared__ unsigned long long red[256];
    red[tid] = best;
    __syncthreads();
    for (int s = 128; s > 0; s >>= 1) {
        if (tid < s) red[tid] = red[tid] > red[tid + s] ? red[tid] : red[tid + s];
        __syncthreads();
    }
    if (tid == 0) {
        int idx = (NCL_ - 1) - (int)(red[0] & 0xffffffffu);
        g_idx[b] = idx;
        out[(size_t)b * T_ + t] = (float)idx;   // output dtype: float32
    }
}

// ---------------- launch (256*3 + 3 = 771 graph nodes, proven infra-safe) ----------------
extern "C" void kernel_launch(void* const* d_in, const int* in_sizes, int n_in,
                              void* d_out, int out_size) {
    (void)out_size;
    const float *x = 0, *W = 0, *U = 0, *b = 0, *Wout = 0, *bout = 0;
    const float* big[2] = {0, 0};
    int nbig = 0;
    for (int i = 0; i < n_in; i++) {
        switch (in_sizes[i]) {
            case 33554432: x    = (const float*)d_in[i]; break;  // 256*256*512
            case 524288:   Wout = (const float*)d_in[i]; break;  // 1024*512
            case 4096:     b    = (const float*)d_in[i]; break;
            case 512:      bout = (const float*)d_in[i]; break;
            case 4194304:  if (nbig < 2) big[nbig++] = (const float*)d_in[i]; break;
            default: break;
        }
    }
    W = big[0];
    U = big[1];
    float* out = (float*)d_out;

    init_kernel<<<512, 256>>>();
    permute_kernel<<<2048, 256>>>(W, U, b);
    precompute_kernel<<<dim3(FOURU_ / BN, (B_ * T_) / BM), 256>>>(x);

    for (int t = 0; t < T_; t++) {
        step_kernel<<<dim3(FOURU_ / SBN, B_ / SBM), 256>>>(t);
        logits_kernel<<<dim3(NCL_ / LBN, B_ / LBM, 8), 256>>>(Wout, t);
        argmax_kernel<<<B_, 256>>>(bout, out, t);
    }
}